// round 13
// baseline (speedup 1.0000x reference)
#include <cuda_runtime.h>
#include <cstdint>

#define T_TOK 4096
#define NHEAD 16
#define NGRP  4
#define HDIM  128
#define NSEQ  8
#define BQ    128
#define BK    32

#define QSTRIDE 132
// K4 layout: K4[row][c4 = col&3][idx = col>>2]; addr = row*KS4 + c4*CS4 + idx
#define KS4 144
#define CS4 36
// V4 layout: V4[row][c8 = col&7][idx = col>>3]; addr = row*VS4 + c8*CV4 + idx
#define VS4 168
#define CV4 20

static constexpr float COEF = 0.08838834764831845f * 1.4426950408889634f;

// smem (floats): Qs[128][132] staging, K4[2][32][144], V4[2][32][168], cus
#define SM_Q    0
#define SM_K4   (SM_Q  + BQ * QSTRIDE)          // 16896
#define SM_V4   (SM_K4 + 2 * BK * KS4)          // +9216
#define SM_CUS  (SM_V4 + 2 * BK * VS4)          // +10752
#define SMEM_BYTES ((SM_CUS + 16) * 4)          // 147,584 B

__device__ __forceinline__ float ex2(float x) {
    float y;
    asm("ex2.approx.ftz.f32 %0, %1;" : "=f"(y) : "f"(x));
    return y;
}
__device__ __forceinline__ float tf32rn(float x) {
    float y;
    asm("cvt.rna.tf32.f32 %0, %1;" : "=f"(y) : "f"(x));
    return y;
}
__device__ __forceinline__ void mma8(float d[4], const float a[4], float b0, float b1) {
    asm volatile(
        "mma.sync.aligned.m16n8k8.row.col.f32.tf32.tf32.f32 "
        "{%0,%1,%2,%3}, {%4,%5,%6,%7}, {%8,%9}, {%0,%1,%2,%3};"
        : "+f"(d[0]), "+f"(d[1]), "+f"(d[2]), "+f"(d[3])
        : "r"(__float_as_uint(a[0])), "r"(__float_as_uint(a[1])),
          "r"(__float_as_uint(a[2])), "r"(__float_as_uint(a[3])),
          "r"(__float_as_uint(b0)), "r"(__float_as_uint(b1)));
}

__global__ __launch_bounds__(256, 1)
void fa_mma12_kernel(const float* __restrict__ q, const float* __restrict__ k,
                     const float* __restrict__ v, const int* __restrict__ cu,
                     float* __restrict__ out)
{
    extern __shared__ float sm[];
    float* Qs  = sm + SM_Q;
    int*   cus = (int*)(sm + SM_CUS);

    const int tid = threadIdx.x, wid = tid >> 5, lane = tid & 31;
    const int r = lane >> 2, c = lane & 3;
    const int qt = gridDim.x - 1 - blockIdx.x;    // heavy (late) q-tiles first
    const int q0 = qt * BQ;
    const int h = blockIdx.y, g = h >> 2;

    if (tid <= NSEQ) cus[tid] = cu[tid];

    // ---- stage Q tile [128][128] (staging only) ----
    {
        const float4* qg = (const float4*)(q + ((size_t)q0 * NHEAD + h) * HDIM);
        #pragma unroll
        for (int i = tid; i < BQ * 32; i += 256) {
            int rr = i >> 5, dd = i & 31;
            *(float4*)(Qs + rr * QSTRIDE + dd * 4) = qg[(size_t)rr * (NHEAD * HDIM / 4) + dd];
        }
    }
    __syncthreads();

    const int rb = wid * 16;

    // ---- cache Q fragments (tf32-RN) in registers for the whole KV loop ----
    float qh[16][4];
    #pragma unroll
    for (int kc = 0; kc < 16; kc++) {
        const float* base = Qs + (rb + r) * QSTRIDE + kc * 8 + c;
        qh[kc][0] = tf32rn(base[0]);
        qh[kc][1] = tf32rn(base[8 * QSTRIDE]);
        qh[kc][2] = tf32rn(base[4]);
        qh[kc][3] = tf32rn(base[8 * QSTRIDE + 4]);
    }

    const int qp0 = q0 + rb + r;
    const int qp1 = qp0 + 8;
    int seg0 = 0, seg1 = 0, st = 0;
    #pragma unroll
    for (int j = 1; j < NSEQ; j++) {
        seg0 += (qp0 >= cus[j]);
        seg1 += (qp1 >= cus[j]);
        st   += (q0  >= cus[j]);
    }
    const int lo0g = cus[seg0], lo1g = cus[seg1];
    const int first_kt = cus[st] >> 5;
    const int last_kt  = (q0 + BQ - 1) >> 5;

    float o[16][4];
    #pragma unroll
    for (int nb = 0; nb < 16; nb++)
        o[nb][0] = o[nb][1] = o[nb][2] = o[nb][3] = 0.f;
    float lsum0 = 0.f, lsum1 = 0.f;

    // ---- per-thread gmem staging regs (warp w stages rows {w, w+8, w+16, w+24}) ----
    const int ld_r = tid >> 5;
    const int ld_d = tid & 31;
    float4 kreg[4], vreg[4];

    {   // prologue: load tile first_kt
        const float4* kg = (const float4*)(k + ((size_t)(first_kt * BK) * NGRP + g) * HDIM);
        const float4* vg = (const float4*)(v + ((size_t)(first_kt * BK) * NGRP + g) * HDIM);
        #pragma unroll
        for (int j = 0; j < 4; j++) {
            int rr = ld_r + j * 8;
            kreg[j] = kg[(size_t)rr * (NGRP * HDIM / 4) + ld_d];
            vreg[j] = vg[(size_t)rr * (NGRP * HDIM / 4) + ld_d];
        }
    }

    int buf = 0;
    for (int kt = first_kt; kt <= last_kt; kt++, buf ^= 1) {
        const int kv0 = kt * BK;
        float* KH = sm + SM_K4 + buf * (BK * KS4);
        float* VH = sm + SM_V4 + buf * (BK * VS4);

        // ---- RN-round staged regs into mod-permuted smem tiles (conflict-free STS.32) ----
        #pragma unroll
        for (int j = 0; j < 4; j++) {
            int rr = ld_r + j * 8;
            float4 kv = kreg[j], vv = vreg[j];
            float* kb = KH + rr * KS4 + ld_d;                         // element e -> + e*CS4
            kb[0 * CS4] = tf32rn(kv.x);
            kb[1 * CS4] = tf32rn(kv.y);
            kb[2 * CS4] = tf32rn(kv.z);
            kb[3 * CS4] = tf32rn(kv.w);
            float* vb = VH + rr * VS4 + (ld_d >> 1) + (ld_d & 1) * 4 * CV4;  // e -> + e*CV4
            vb[0 * CV4] = tf32rn(vv.x);
            vb[1 * CV4] = tf32rn(vv.y);
            vb[2 * CV4] = tf32rn(vv.z);
            vb[3 * CV4] = tf32rn(vv.w);
        }
        __syncthreads();

        // ---- prefetch next tile (latency hidden behind compute) ----
        if (kt < last_kt) {
            const float4* kg = (const float4*)(k + ((size_t)(kv0 + BK) * NGRP + g) * HDIM);
            const float4* vg = (const float4*)(v + ((size_t)(kv0 + BK) * NGRP + g) * HDIM);
            #pragma unroll
            for (int j = 0; j < 4; j++) {
                int rr = ld_r + j * 8;
                kreg[j] = kg[(size_t)rr * (NGRP * HDIM / 4) + ld_d];
                vreg[j] = vg[(size_t)rr * (NGRP * HDIM / 4) + ld_d];
            }
        }

        // ---- MMA1: S = Q * K  (vectorized B-fragments, nb pairs for ILP) ----
        float sacc[4][4];
        #pragma unroll
        for (int nb = 0; nb < 4; nb++)
            sacc[nb][0] = sacc[nb][1] = sacc[nb][2] = sacc[nb][3] = 0.f;

        #pragma unroll
        for (int nbp = 0; nbp < 4; nbp += 2) {
            const float* k0 = KH + (nbp * 8 + r) * KS4 + c * CS4;
            const float* k1 = KH + ((nbp + 1) * 8 + r) * KS4 + c * CS4;
            #pragma unroll
            for (int m = 0; m < 8; m++) {
                float4 f0 = *(const float4*)(k0 + 4 * m);   // K[nbp*8+r][16m+c .. +12]
                float4 f1 = *(const float4*)(k1 + 4 * m);
                mma8(sacc[nbp],     qh[2 * m],     f0.x, f0.y);
                mma8(sacc[nbp + 1], qh[2 * m],     f1.x, f1.y);
                mma8(sacc[nbp],     qh[2 * m + 1], f0.z, f0.w);
                mma8(sacc[nbp + 1], qh[2 * m + 1], f1.z, f1.w);
            }
        }

        // ---- mask + exp; quantize P (RN) before summing -> exact in MMA2 ----
        const int hi0 = qp0 - kv0, hi1 = qp1 - kv0;
        const int l0  = lo0g - kv0, l1 = lo1g - kv0;
        #pragma unroll
        for (int nb = 0; nb < 4; nb++) {
            const int j0 = nb * 8 + 2 * c, j1 = j0 + 1;
            float p0 = (j0 >= l0 && j0 <= hi0) ? tf32rn(ex2(sacc[nb][0] * COEF)) : 0.f;
            float p1 = (j1 >= l0 && j1 <= hi0) ? tf32rn(ex2(sacc[nb][1] * COEF)) : 0.f;
            float p2 = (j0 >= l1 && j0 <= hi1) ? tf32rn(ex2(sacc[nb][2] * COEF)) : 0.f;
            float p3 = (j1 >= l1 && j1 <= hi1) ? tf32rn(ex2(sacc[nb][3] * COEF)) : 0.f;
            lsum0 += p0 + p1;
            lsum1 += p2 + p3;
            sacc[nb][0] = p0; sacc[nb][1] = p1; sacc[nb][2] = p2; sacc[nb][3] = p3;
        }

        // ---- P C-frag -> A-frag (shuffles), all 4 fragments up front ----
        const int s0 = (lane & ~3) | (c >> 1);
        const int s1 = s0 + 2;
        const bool odd = (c & 1);
        float pa[4][4];
        #pragma unroll
        for (int kc2 = 0; kc2 < 4; kc2++) {
            float t0 = __shfl_sync(0xffffffffu, sacc[kc2][0], s0);
            float t1 = __shfl_sync(0xffffffffu, sacc[kc2][1], s0);
            float t2 = __shfl_sync(0xffffffffu, sacc[kc2][2], s0);
            float t3 = __shfl_sync(0xffffffffu, sacc[kc2][3], s0);
            float u0 = __shfl_sync(0xffffffffu, sacc[kc2][0], s1);
            float u1 = __shfl_sync(0xffffffffu, sacc[kc2][1], s1);
            float u2 = __shfl_sync(0xffffffffu, sacc[kc2][2], s1);
            float u3 = __shfl_sync(0xffffffffu, sacc[kc2][3], s1);
            pa[kc2][0] = odd ? t1 : t0;
            pa[kc2][1] = odd ? t3 : t2;
            pa[kc2][2] = odd ? u1 : u0;
            pa[kc2][3] = odd ? u3 : u2;
        }

        // ---- MMA2: O += P * V  (vectorized V-fragments; o[] distance-16 chains) ----
        #pragma unroll
        for (int kc2 = 0; kc2 < 4; kc2++) {
            const float* v0 = VH + (kc2 * 8 + c) * VS4 + r * CV4;
            const float* v1 = VH + (kc2 * 8 + c + 4) * VS4 + r * CV4;
            #pragma unroll
            for (int m = 0; m < 4; m++) {
                float4 f0 = *(const float4*)(v0 + 4 * m);   // V[8kc2+c ][8(4m+e)+r]
                float4 f1 = *(const float4*)(v1 + 4 * m);   // V[8kc2+c4][8(4m+e)+r]
                mma8(o[4 * m + 0], pa[kc2], f0.x, f1.x);
                mma8(o[4 * m + 1], pa[kc2], f0.y, f1.y);
                mma8(o[4 * m + 2], pa[kc2], f0.z, f1.z);
                mma8(o[4 * m + 3], pa[kc2], f0.w, f1.w);
            }
        }
    }

    // ---- epilogue ----
    lsum0 += __shfl_xor_sync(0xffffffffu, lsum0, 1);
    lsum0 += __shfl_xor_sync(0xffffffffu, lsum0, 2);
    lsum1 += __shfl_xor_sync(0xffffffffu, lsum1, 1);
    lsum1 += __shfl_xor_sync(0xffffffffu, lsum1, 2);
    const float inv0 = 1.0f / lsum0;
    const float inv1 = 1.0f / lsum1;

    float* o0 = out + ((size_t)qp0 * NHEAD + h) * HDIM;
    float* o1 = out + ((size_t)qp1 * NHEAD + h) * HDIM;
    #pragma unroll
    for (int nb = 0; nb < 16; nb++) {
        const int j0 = nb * 8 + 2 * c;
        *(float2*)(o0 + j0) = make_float2(o[nb][0] * inv0, o[nb][1] * inv0);
        *(float2*)(o1 + j0) = make_float2(o[nb][2] * inv1, o[nb][3] * inv1);
    }
}

extern "C" void kernel_launch(void* const* d_in, const int* in_sizes, int n_in,
                              void* d_out, int out_size)
{
    const float* q  = (const float*)d_in[0];
    const float* k  = (const float*)d_in[1];
    const float* v  = (const float*)d_in[2];
    const int*   cu = (const int*)d_in[3];
    float* out = (float*)d_out;

    static bool attr_set = false;
    if (!attr_set) {
        cudaFuncSetAttribute(fa_mma12_kernel,
                             cudaFuncAttributeMaxDynamicSharedMemorySize, SMEM_BYTES);
        attr_set = true;
    }

    dim3 grid(T_TOK / BQ, NHEAD);
    fa_mma12_kernel<<<grid, 256, SMEM_BYTES>>>(q, k, v, cu, out);
}

// round 14
// speedup vs baseline: 1.5195x; 1.5195x over previous
#include <cuda_runtime.h>
#include <cstdint>

#define T_TOK 4096
#define NHEAD 16
#define NGRP  4
#define HDIM  128
#define NSEQ  8
#define BQ    128
#define BK    32
#define NST   4     // cp.async pipeline stages

#define QSTRIDE 132
#define KSTRIDE 132
#define VSTRIDE 136

static constexpr float COEF = 0.08838834764831845f * 1.4426950408889634f;

// smem (floats): Qs[128][132], K[NST][32][132] raw fp32, V[NST][32][136] raw fp32, cus
#define SM_Q    0
#define SM_K    (SM_Q + BQ * QSTRIDE)               // 16896 fl
#define SM_V    (SM_K + NST * BK * KSTRIDE)         // +16896 fl
#define SM_CUS  (SM_V + NST * BK * VSTRIDE)         // +17408 fl
#define SMEM_BYTES ((SM_CUS + 16) * 4)              // 204,928 B

__device__ __forceinline__ float ex2(float x) {
    float y;
    asm("ex2.approx.ftz.f32 %0, %1;" : "=f"(y) : "f"(x));
    return y;
}
__device__ __forceinline__ float tf32rn(float x) {
    float y;
    asm("cvt.rna.tf32.f32 %0, %1;" : "=f"(y) : "f"(x));
    return y;
}
__device__ __forceinline__ uint32_t smem_u32(const void* p) {
    uint32_t a;
    asm("{ .reg .u64 t; cvta.to.shared.u64 t, %1; cvt.u32.u64 %0, t; }" : "=r"(a) : "l"(p));
    return a;
}
__device__ __forceinline__ void cpa16(uint32_t dst, const void* src) {
    asm volatile("cp.async.cg.shared.global [%0], [%1], 16;" :: "r"(dst), "l"(src) : "memory");
}
#define CP_COMMIT() asm volatile("cp.async.commit_group;" ::: "memory")
#define CP_WAIT2()  asm volatile("cp.async.wait_group 2;" ::: "memory")

__device__ __forceinline__ void mma8(float d[4], const float a[4], float b0, float b1) {
    asm volatile(
        "mma.sync.aligned.m16n8k8.row.col.f32.tf32.tf32.f32 "
        "{%0,%1,%2,%3}, {%4,%5,%6,%7}, {%8,%9}, {%0,%1,%2,%3};"
        : "+f"(d[0]), "+f"(d[1]), "+f"(d[2]), "+f"(d[3])
        : "r"(__float_as_uint(a[0])), "r"(__float_as_uint(a[1])),
          "r"(__float_as_uint(a[2])), "r"(__float_as_uint(a[3])),
          "r"(__float_as_uint(b0)), "r"(__float_as_uint(b1)));
}

__global__ __launch_bounds__(256, 1)
void fa_mma14_kernel(const float* __restrict__ q, const float* __restrict__ k,
                     const float* __restrict__ v, const int* __restrict__ cu,
                     float* __restrict__ out)
{
    extern __shared__ float sm[];
    float* Qs  = sm + SM_Q;
    int*   cus = (int*)(sm + SM_CUS);
    const uint32_t sb = smem_u32(sm);

    const int tid = threadIdx.x, wid = tid >> 5, lane = tid & 31;
    const int r = lane >> 2, c = lane & 3;
    const int qt = gridDim.x - 1 - blockIdx.x;    // heavy (late) q-tiles first
    const int q0 = qt * BQ;
    const int h = blockIdx.y, g = h >> 2;

    if (tid <= NSEQ) cus[tid] = cu[tid];

    // per-thread copy slice: warp w covers rows {w, w+8, w+16, w+24}, lane covers 16B chunk
    const int ld_r = tid >> 5;
    const int ld_d = tid & 31;

    // first_kt needs cu[]; compute from gmem directly (cheap, avoids barrier dependence)
    int st = 0;
    #pragma unroll
    for (int j = 1; j < NSEQ; j++) st += (q0 >= cu[j]);
    const int first_kt = cu[st] >> 5;
    const int last_kt  = (q0 + BQ - 1) >> 5;

    // ---- cp.async prologue: issue stages for first_kt .. first_kt+2 ----
    #pragma unroll
    for (int s = 0; s < NST - 1; s++) {
        const int t = first_kt + s;
        if (t <= last_kt) {
            const float4* kg = (const float4*)(k + ((size_t)(t * BK) * NGRP + g) * HDIM);
            const float4* vg = (const float4*)(v + ((size_t)(t * BK) * NGRP + g) * HDIM);
            const uint32_t kb = sb + (SM_K + (s & (NST - 1)) * BK * KSTRIDE) * 4;
            const uint32_t vb = sb + (SM_V + (s & (NST - 1)) * BK * VSTRIDE) * 4;
            #pragma unroll
            for (int j = 0; j < 4; j++) {
                int rr = ld_r + j * 8;
                cpa16(kb + (rr * KSTRIDE + ld_d * 4) * 4, kg + (size_t)rr * (NGRP * HDIM / 4) + ld_d);
                cpa16(vb + (rr * VSTRIDE + ld_d * 4) * 4, vg + (size_t)rr * (NGRP * HDIM / 4) + ld_d);
            }
        }
        CP_COMMIT();
    }

    // ---- stage Q tile [128][128] (regular loads; overlaps with cp.async) ----
    {
        const float4* qg = (const float4*)(q + ((size_t)q0 * NHEAD + h) * HDIM);
        #pragma unroll
        for (int i = tid; i < BQ * 32; i += 256) {
            int rr = i >> 5, dd = i & 31;
            *(float4*)(Qs + rr * QSTRIDE + dd * 4) = qg[(size_t)rr * (NHEAD * HDIM / 4) + dd];
        }
    }
    __syncthreads();

    const int rb = wid * 16;

    // ---- cache Q fragments (tf32-RN) in registers for the whole KV loop ----
    float qh[16][4];
    #pragma unroll
    for (int kc = 0; kc < 16; kc++) {
        const float* base = Qs + (rb + r) * QSTRIDE + kc * 8 + c;
        qh[kc][0] = tf32rn(base[0]);
        qh[kc][1] = tf32rn(base[8 * QSTRIDE]);
        qh[kc][2] = tf32rn(base[4]);
        qh[kc][3] = tf32rn(base[8 * QSTRIDE + 4]);
    }

    const int qp0 = q0 + rb + r;
    const int qp1 = qp0 + 8;
    int seg0 = 0, seg1 = 0;
    #pragma unroll
    for (int j = 1; j < NSEQ; j++) {
        seg0 += (qp0 >= cus[j]);
        seg1 += (qp1 >= cus[j]);
    }
    const int lo0g = cus[seg0], lo1g = cus[seg1];

    float o[16][4];
    #pragma unroll
    for (int nb = 0; nb < 16; nb++)
        o[nb][0] = o[nb][1] = o[nb][2] = o[nb][3] = 0.f;
    float lsum0 = 0.f, lsum1 = 0.f;

    for (int kt = first_kt; kt <= last_kt; kt++) {
        const int idx = kt - first_kt;
        const int buf = idx & (NST - 1);
        const int kv0 = kt * BK;

        // group for tile kt complete once <=2 newer groups pending
        CP_WAIT2();
        __syncthreads();   // data visible to all warps; prior tile's consumers done

        // ---- issue tile kt+3 into buf (idx+3)&3 (overwrites tile kt-1's buffer) ----
        {
            const int t = kt + NST - 1;
            if (t <= last_kt) {
                const int s = (idx + NST - 1) & (NST - 1);
                const float4* kg = (const float4*)(k + ((size_t)(t * BK) * NGRP + g) * HDIM);
                const float4* vg = (const float4*)(v + ((size_t)(t * BK) * NGRP + g) * HDIM);
                const uint32_t kb = sb + (SM_K + s * BK * KSTRIDE) * 4;
                const uint32_t vb = sb + (SM_V + s * BK * VSTRIDE) * 4;
                #pragma unroll
                for (int j = 0; j < 4; j++) {
                    int rr = ld_r + j * 8;
                    cpa16(kb + (rr * KSTRIDE + ld_d * 4) * 4, kg + (size_t)rr * (NGRP * HDIM / 4) + ld_d);
                    cpa16(vb + (rr * VSTRIDE + ld_d * 4) * 4, vg + (size_t)rr * (NGRP * HDIM / 4) + ld_d);
                }
            }
            CP_COMMIT();   // unconditional: keeps group accounting uniform
        }

        const float* KH = sm + SM_K + buf * (BK * KSTRIDE);
        const float* VH = sm + SM_V + buf * (BK * VSTRIDE);

        // ---- MMA1: S = Q * K  (K raw fp32; HW RZ-truncates B operand) ----
        float sacc[4][4];
        #pragma unroll
        for (int nb = 0; nb < 4; nb++)
            sacc[nb][0] = sacc[nb][1] = sacc[nb][2] = sacc[nb][3] = 0.f;

        #pragma unroll
        for (int kc = 0; kc < 16; kc++) {
            const float* kbh = KH + kc * 8 + c;
            #pragma unroll
            for (int nb = 0; nb < 4; nb++) {
                float kh0 = kbh[(nb * 8 + r) * KSTRIDE];
                float kh1 = kbh[(nb * 8 + r) * KSTRIDE + 4];
                mma8(sacc[nb], qh[kc], kh0, kh1);
            }
        }

        // ---- mask + exp; quantize P (RN) before summing -> consistent in MMA2 ----
        const int hi0 = qp0 - kv0, hi1 = qp1 - kv0;
        const int l0  = lo0g - kv0, l1 = lo1g - kv0;
        #pragma unroll
        for (int nb = 0; nb < 4; nb++) {
            const int j0 = nb * 8 + 2 * c, j1 = j0 + 1;
            float p0 = (j0 >= l0 && j0 <= hi0) ? tf32rn(ex2(sacc[nb][0] * COEF)) : 0.f;
            float p1 = (j1 >= l0 && j1 <= hi0) ? tf32rn(ex2(sacc[nb][1] * COEF)) : 0.f;
            float p2 = (j0 >= l1 && j0 <= hi1) ? tf32rn(ex2(sacc[nb][2] * COEF)) : 0.f;
            float p3 = (j1 >= l1 && j1 <= hi1) ? tf32rn(ex2(sacc[nb][3] * COEF)) : 0.f;
            lsum0 += p0 + p1;
            lsum1 += p2 + p3;
            sacc[nb][0] = p0; sacc[nb][1] = p1; sacc[nb][2] = p2; sacc[nb][3] = p3;
        }

        // ---- MMA2: O += P * V  (P C-frag -> A-frag via shuffles; V raw fp32) ----
        const int s0 = (lane & ~3) | (c >> 1);
        const int s1 = s0 + 2;
        const bool odd = (c & 1);
        #pragma unroll
        for (int kc2 = 0; kc2 < 4; kc2++) {
            float t0 = __shfl_sync(0xffffffffu, sacc[kc2][0], s0);
            float t1 = __shfl_sync(0xffffffffu, sacc[kc2][1], s0);
            float t2 = __shfl_sync(0xffffffffu, sacc[kc2][2], s0);
            float t3 = __shfl_sync(0xffffffffu, sacc[kc2][3], s0);
            float u0 = __shfl_sync(0xffffffffu, sacc[kc2][0], s1);
            float u1 = __shfl_sync(0xffffffffu, sacc[kc2][1], s1);
            float u2 = __shfl_sync(0xffffffffu, sacc[kc2][2], s1);
            float u3 = __shfl_sync(0xffffffffu, sacc[kc2][3], s1);
            float pa[4];
            pa[0] = odd ? t1 : t0;
            pa[1] = odd ? t3 : t2;
            pa[2] = odd ? u1 : u0;
            pa[3] = odd ? u3 : u2;

            const float* vb = VH + (kc2 * 8 + c) * VSTRIDE + r;
            #pragma unroll
            for (int nb = 0; nb < 16; nb++) {
                float b0 = vb[nb * 8];
                float b1 = vb[nb * 8 + 4 * VSTRIDE];
                mma8(o[nb], pa, b0, b1);
            }
        }
    }

    // ---- epilogue ----
    lsum0 += __shfl_xor_sync(0xffffffffu, lsum0, 1);
    lsum0 += __shfl_xor_sync(0xffffffffu, lsum0, 2);
    lsum1 += __shfl_xor_sync(0xffffffffu, lsum1, 1);
    lsum1 += __shfl_xor_sync(0xffffffffu, lsum1, 2);
    const float inv0 = 1.0f / lsum0;
    const float inv1 = 1.0f / lsum1;

    float* o0 = out + ((size_t)qp0 * NHEAD + h) * HDIM;
    float* o1 = out + ((size_t)qp1 * NHEAD + h) * HDIM;
    #pragma unroll
    for (int nb = 0; nb < 16; nb++) {
        const int j0 = nb * 8 + 2 * c;
        *(float2*)(o0 + j0) = make_float2(o[nb][0] * inv0, o[nb][1] * inv0);
        *(float2*)(o1 + j0) = make_float2(o[nb][2] * inv1, o[nb][3] * inv1);
    }
}

extern "C" void kernel_launch(void* const* d_in, const int* in_sizes, int n_in,
                              void* d_out, int out_size)
{
    const float* q  = (const float*)d_in[0];
    const float* k  = (const float*)d_in[1];
    const float* v  = (const float*)d_in[2];
    const int*   cu = (const int*)d_in[3];
    float* out = (float*)d_out;

    static bool attr_set = false;
    if (!attr_set) {
        cudaFuncSetAttribute(fa_mma14_kernel,
                             cudaFuncAttributeMaxDynamicSharedMemorySize, SMEM_BYTES);
        attr_set = true;
    }

    dim3 grid(T_TOK / BQ, NHEAD);
    fa_mma14_kernel<<<grid, 256, SMEM_BYTES>>>(q, k, v, cu, out);
}

// round 15
// speedup vs baseline: 1.6003x; 1.0532x over previous
#include <cuda_runtime.h>
#include <cstdint>

#define T_TOK 4096
#define NHEAD 16
#define NGRP  4
#define HDIM  128
#define NSEQ  8
#define BQ    64
#define BK    32
#define NST   2
#define NTHR  128

#define QSTRIDE 132
#define KSTRIDE 132
#define VSTRIDE 136

static constexpr float COEF = 0.08838834764831845f * 1.4426950408889634f;

// smem (floats): Qs[64][132], K[2][32][132] raw fp32, V[2][32][136] raw fp32, cus
#define SM_Q    0
#define SM_K    (SM_Q + BQ * QSTRIDE)               // 8448 fl
#define SM_V    (SM_K + NST * BK * KSTRIDE)         // +8448 fl
#define SM_CUS  (SM_V + NST * BK * VSTRIDE)         // +8704 fl
#define SMEM_BYTES ((SM_CUS + 16) * 4)              // 102,464 B -> 2 CTAs/SM

__device__ __forceinline__ float ex2(float x) {
    float y;
    asm("ex2.approx.ftz.f32 %0, %1;" : "=f"(y) : "f"(x));
    return y;
}
__device__ __forceinline__ float tf32rn(float x) {
    float y;
    asm("cvt.rna.tf32.f32 %0, %1;" : "=f"(y) : "f"(x));
    return y;
}
__device__ __forceinline__ uint32_t smem_u32(const void* p) {
    uint32_t a;
    asm("{ .reg .u64 t; cvta.to.shared.u64 t, %1; cvt.u32.u64 %0, t; }" : "=r"(a) : "l"(p));
    return a;
}
__device__ __forceinline__ void cpa16(uint32_t dst, const void* src) {
    asm volatile("cp.async.cg.shared.global [%0], [%1], 16;" :: "r"(dst), "l"(src) : "memory");
}
#define CP_COMMIT() asm volatile("cp.async.commit_group;" ::: "memory")
#define CP_WAIT0()  asm volatile("cp.async.wait_group 0;" ::: "memory")

__device__ __forceinline__ void mma8(float d[4], const float a[4], float b0, float b1) {
    asm volatile(
        "mma.sync.aligned.m16n8k8.row.col.f32.tf32.tf32.f32 "
        "{%0,%1,%2,%3}, {%4,%5,%6,%7}, {%8,%9}, {%0,%1,%2,%3};"
        : "+f"(d[0]), "+f"(d[1]), "+f"(d[2]), "+f"(d[3])
        : "r"(__float_as_uint(a[0])), "r"(__float_as_uint(a[1])),
          "r"(__float_as_uint(a[2])), "r"(__float_as_uint(a[3])),
          "r"(__float_as_uint(b0)), "r"(__float_as_uint(b1)));
}

__global__ __launch_bounds__(NTHR, 2)
void fa_mma15_kernel(const float* __restrict__ q, const float* __restrict__ k,
                     const float* __restrict__ v, const int* __restrict__ cu,
                     float* __restrict__ out)
{
    extern __shared__ float sm[];
    float* Qs  = sm + SM_Q;
    int*   cus = (int*)(sm + SM_CUS);
    const uint32_t sb = smem_u32(sm);

    const int tid = threadIdx.x, wid = tid >> 5, lane = tid & 31;
    const int r = lane >> 2, c = lane & 3;
    const int qt = gridDim.x - 1 - blockIdx.x;    // heavy (late) q-tiles first
    const int q0 = qt * BQ;
    const int h = blockIdx.y, g = h >> 2;

    if (tid <= NSEQ) cus[tid] = cu[tid];

    // per-thread copy slice: thread covers rows {ld_r + 4j, j=0..7}, 16B chunk ld_d
    const int ld_r = tid >> 5;        // 0..3
    const int ld_d = tid & 31;

    // first_kt directly from gmem cu (no barrier dependence)
    int st = 0;
    #pragma unroll
    for (int j = 1; j < NSEQ; j++) st += (q0 >= cu[j]);
    const int first_kt = cu[st] >> 5;
    const int last_kt  = (q0 + BQ - 1) >> 5;

    // ---- cp.async prologue: issue tile first_kt into buf 0 ----
    {
        const float4* kg = (const float4*)(k + ((size_t)(first_kt * BK) * NGRP + g) * HDIM);
        const float4* vg = (const float4*)(v + ((size_t)(first_kt * BK) * NGRP + g) * HDIM);
        const uint32_t kb = sb + SM_K * 4;
        const uint32_t vb = sb + SM_V * 4;
        #pragma unroll
        for (int j = 0; j < 8; j++) {
            int rr = ld_r + j * 4;
            cpa16(kb + (rr * KSTRIDE + ld_d * 4) * 4, kg + (size_t)rr * (NGRP * HDIM / 4) + ld_d);
            cpa16(vb + (rr * VSTRIDE + ld_d * 4) * 4, vg + (size_t)rr * (NGRP * HDIM / 4) + ld_d);
        }
        CP_COMMIT();
    }

    // ---- stage Q tile [64][128] (regular loads; overlaps with cp.async) ----
    {
        const float4* qg = (const float4*)(q + ((size_t)q0 * NHEAD + h) * HDIM);
        #pragma unroll
        for (int i = tid; i < BQ * 32; i += NTHR) {
            int rr = i >> 5, dd = i & 31;
            *(float4*)(Qs + rr * QSTRIDE + dd * 4) = qg[(size_t)rr * (NHEAD * HDIM / 4) + dd];
        }
    }
    __syncthreads();

    const int rb = wid * 16;

    // ---- cache Q fragments (tf32-RN) in registers for the whole KV loop ----
    float qh[16][4];
    #pragma unroll
    for (int kc = 0; kc < 16; kc++) {
        const float* base = Qs + (rb + r) * QSTRIDE + kc * 8 + c;
        qh[kc][0] = tf32rn(base[0]);
        qh[kc][1] = tf32rn(base[8 * QSTRIDE]);
        qh[kc][2] = tf32rn(base[4]);
        qh[kc][3] = tf32rn(base[8 * QSTRIDE + 4]);
    }

    const int qp0 = q0 + rb + r;
    const int qp1 = qp0 + 8;
    int seg0 = 0, seg1 = 0;
    #pragma unroll
    for (int j = 1; j < NSEQ; j++) {
        seg0 += (qp0 >= cus[j]);
        seg1 += (qp1 >= cus[j]);
    }
    const int lo0g = cus[seg0], lo1g = cus[seg1];

    float o[16][4];
    #pragma unroll
    for (int nb = 0; nb < 16; nb++)
        o[nb][0] = o[nb][1] = o[nb][2] = o[nb][3] = 0.f;
    float lsum0 = 0.f, lsum1 = 0.f;

    int buf = 0;
    for (int kt = first_kt; kt <= last_kt; kt++, buf ^= 1) {
        const int kv0 = kt * BK;

        CP_WAIT0();        // this thread's issued copies (tile kt) complete
        __syncthreads();   // all threads' copies visible; prior tile's readers done

        // ---- issue tile kt+1 into the other buffer (overlaps compute below) ----
        if (kt < last_kt) {
            const float4* kg = (const float4*)(k + ((size_t)(kv0 + BK) * NGRP + g) * HDIM);
            const float4* vg = (const float4*)(v + ((size_t)(kv0 + BK) * NGRP + g) * HDIM);
            const uint32_t kb = sb + (SM_K + (buf ^ 1) * BK * KSTRIDE) * 4;
            const uint32_t vb = sb + (SM_V + (buf ^ 1) * BK * VSTRIDE) * 4;
            #pragma unroll
            for (int j = 0; j < 8; j++) {
                int rr = ld_r + j * 4;
                cpa16(kb + (rr * KSTRIDE + ld_d * 4) * 4, kg + (size_t)rr * (NGRP * HDIM / 4) + ld_d);
                cpa16(vb + (rr * VSTRIDE + ld_d * 4) * 4, vg + (size_t)rr * (NGRP * HDIM / 4) + ld_d);
            }
            CP_COMMIT();
        }

        const float* KH = sm + SM_K + buf * (BK * KSTRIDE);
        const float* VH = sm + SM_V + buf * (BK * VSTRIDE);

        // ---- MMA1: S = Q * K  (K raw fp32; HW RZ-truncates B operand) ----
        float sacc[4][4];
        #pragma unroll
        for (int nb = 0; nb < 4; nb++)
            sacc[nb][0] = sacc[nb][1] = sacc[nb][2] = sacc[nb][3] = 0.f;

        #pragma unroll
        for (int kc = 0; kc < 16; kc++) {
            const float* kbh = KH + kc * 8 + c;
            #pragma unroll
            for (int nb = 0; nb < 4; nb++) {
                float kh0 = kbh[(nb * 8 + r) * KSTRIDE];
                float kh1 = kbh[(nb * 8 + r) * KSTRIDE + 4];
                mma8(sacc[nb], qh[kc], kh0, kh1);
            }
        }

        // ---- mask + exp; quantize P (RN) before summing -> consistent in MMA2 ----
        const int hi0 = qp0 - kv0, hi1 = qp1 - kv0;
        const int l0  = lo0g - kv0, l1 = lo1g - kv0;
        #pragma unroll
        for (int nb = 0; nb < 4; nb++) {
            const int j0 = nb * 8 + 2 * c, j1 = j0 + 1;
            float p0 = (j0 >= l0 && j0 <= hi0) ? tf32rn(ex2(sacc[nb][0] * COEF)) : 0.f;
            float p1 = (j1 >= l0 && j1 <= hi0) ? tf32rn(ex2(sacc[nb][1] * COEF)) : 0.f;
            float p2 = (j0 >= l1 && j0 <= hi1) ? tf32rn(ex2(sacc[nb][2] * COEF)) : 0.f;
            float p3 = (j1 >= l1 && j1 <= hi1) ? tf32rn(ex2(sacc[nb][3] * COEF)) : 0.f;
            lsum0 += p0 + p1;
            lsum1 += p2 + p3;
            sacc[nb][0] = p0; sacc[nb][1] = p1; sacc[nb][2] = p2; sacc[nb][3] = p3;
        }

        // ---- MMA2: O += P * V  (P C-frag -> A-frag via shuffles; V raw fp32) ----
        const int s0 = (lane & ~3) | (c >> 1);
        const int s1 = s0 + 2;
        const bool odd = (c & 1);
        #pragma unroll
        for (int kc2 = 0; kc2 < 4; kc2++) {
            float t0 = __shfl_sync(0xffffffffu, sacc[kc2][0], s0);
            float t1 = __shfl_sync(0xffffffffu, sacc[kc2][1], s0);
            float t2 = __shfl_sync(0xffffffffu, sacc[kc2][2], s0);
            float t3 = __shfl_sync(0xffffffffu, sacc[kc2][3], s0);
            float u0 = __shfl_sync(0xffffffffu, sacc[kc2][0], s1);
            float u1 = __shfl_sync(0xffffffffu, sacc[kc2][1], s1);
            float u2 = __shfl_sync(0xffffffffu, sacc[kc2][2], s1);
            float u3 = __shfl_sync(0xffffffffu, sacc[kc2][3], s1);
            float pa[4];
            pa[0] = odd ? t1 : t0;
            pa[1] = odd ? t3 : t2;
            pa[2] = odd ? u1 : u0;
            pa[3] = odd ? u3 : u2;

            const float* vb = VH + (kc2 * 8 + c) * VSTRIDE + r;
            #pragma unroll
            for (int nb = 0; nb < 16; nb++) {
                float b0 = vb[nb * 8];
                float b1 = vb[nb * 8 + 4 * VSTRIDE];
                mma8(o[nb], pa, b0, b1);
            }
        }
    }

    // ---- epilogue ----
    lsum0 += __shfl_xor_sync(0xffffffffu, lsum0, 1);
    lsum0 += __shfl_xor_sync(0xffffffffu, lsum0, 2);
    lsum1 += __shfl_xor_sync(0xffffffffu, lsum1, 1);
    lsum1 += __shfl_xor_sync(0xffffffffu, lsum1, 2);
    const float inv0 = 1.0f / lsum0;
    const float inv1 = 1.0f / lsum1;

    float* o0 = out + ((size_t)qp0 * NHEAD + h) * HDIM;
    float* o1 = out + ((size_t)qp1 * NHEAD + h) * HDIM;
    #pragma unroll
    for (int nb = 0; nb < 16; nb++) {
        const int j0 = nb * 8 + 2 * c;
        *(float2*)(o0 + j0) = make_float2(o[nb][0] * inv0, o[nb][1] * inv0);
        *(float2*)(o1 + j0) = make_float2(o[nb][2] * inv1, o[nb][3] * inv1);
    }
}

extern "C" void kernel_launch(void* const* d_in, const int* in_sizes, int n_in,
                              void* d_out, int out_size)
{
    const float* q  = (const float*)d_in[0];
    const float* k  = (const float*)d_in[1];
    const float* v  = (const float*)d_in[2];
    const int*   cu = (const int*)d_in[3];
    float* out = (float*)d_out;

    static bool attr_set = false;
    if (!attr_set) {
        cudaFuncSetAttribute(fa_mma15_kernel,
                             cudaFuncAttributeMaxDynamicSharedMemorySize, SMEM_BYTES);
        attr_set = true;
    }

    dim3 grid(T_TOK / BQ, NHEAD);
    fa_mma15_kernel<<<grid, NTHR, SMEM_BYTES>>>(q, k, v, cu, out);
}

// round 16
// speedup vs baseline: 1.9758x; 1.2346x over previous
#include <cuda_runtime.h>
#include <cuda_fp16.h>
#include <cstdint>

#define T_TOK 4096
#define NHEAD 16
#define NGRP  4
#define HDIM  128
#define NSEQ  8
#define BQ    64
#define BK    32
#define NTHR  128

#define QSTRIDE 132
#define KPADH   136    // halfs per K row (word-stride 68 ≡ 4 mod 32 -> frag banks 4r+c)
#define VSTRIDE 136

static constexpr float COEF = 0.08838834764831845f * 1.4426950408889634f;

// smem: Qs[64][132] fp32 (staging), KH[2][32][136] half, V[2][32][136] fp32, cus
#define SM_Q    0                                   // floats
#define SM_V    (SM_Q + BQ * QSTRIDE)               // floats
#define SM_CUS  (SM_V + 2 * BK * VSTRIDE)           // floats
#define SM_KH_B ((SM_CUS + 16) * 4)                 // byte offset of KH
#define SMEM_BYTES (SM_KH_B + 2 * BK * KPADH * 2)

__device__ __forceinline__ float ex2(float x) {
    float y;
    asm("ex2.approx.ftz.f32 %0, %1;" : "=f"(y) : "f"(x));
    return y;
}
__device__ __forceinline__ float tf32rn(float x) {
    float y;
    asm("cvt.rna.tf32.f32 %0, %1;" : "=f"(y) : "f"(x));
    return y;
}
__device__ __forceinline__ uint32_t f2h2(float x, float y) {
    __half2 h = __floats2half2_rn(x, y);
    return *(uint32_t*)&h;
}
__device__ __forceinline__ uint32_t smem_u32(const void* p) {
    uint32_t a;
    asm("{ .reg .u64 t; cvta.to.shared.u64 t, %1; cvt.u32.u64 %0, t; }" : "=r"(a) : "l"(p));
    return a;
}
__device__ __forceinline__ void cpa16(uint32_t dst, const void* src) {
    asm volatile("cp.async.cg.shared.global [%0], [%1], 16;" :: "r"(dst), "l"(src) : "memory");
}
#define CP_COMMIT() asm volatile("cp.async.commit_group;" ::: "memory")
#define CP_WAIT0()  asm volatile("cp.async.wait_group 0;" ::: "memory")

// fp16 m16n8k16: D(f32) += A(f16) * B(f16)
__device__ __forceinline__ void mma16(float d[4], const uint32_t a[4], uint32_t b0, uint32_t b1) {
    asm volatile(
        "mma.sync.aligned.m16n8k16.row.col.f32.f16.f16.f32 "
        "{%0,%1,%2,%3}, {%4,%5,%6,%7}, {%8,%9}, {%0,%1,%2,%3};"
        : "+f"(d[0]), "+f"(d[1]), "+f"(d[2]), "+f"(d[3])
        : "r"(a[0]), "r"(a[1]), "r"(a[2]), "r"(a[3]), "r"(b0), "r"(b1));
}
// tf32 m16n8k8 (raw fp32 bits; HW RZ-truncates)
__device__ __forceinline__ void mma8(float d[4], const float a[4], float b0, float b1) {
    asm volatile(
        "mma.sync.aligned.m16n8k8.row.col.f32.tf32.tf32.f32 "
        "{%0,%1,%2,%3}, {%4,%5,%6,%7}, {%8,%9}, {%0,%1,%2,%3};"
        : "+f"(d[0]), "+f"(d[1]), "+f"(d[2]), "+f"(d[3])
        : "r"(__float_as_uint(a[0])), "r"(__float_as_uint(a[1])),
          "r"(__float_as_uint(a[2])), "r"(__float_as_uint(a[3])),
          "r"(__float_as_uint(b0)), "r"(__float_as_uint(b1)));
}

__global__ __launch_bounds__(NTHR, 2)
void fa_mma16_kernel(const float* __restrict__ q, const float* __restrict__ k,
                     const float* __restrict__ v, const int* __restrict__ cu,
                     float* __restrict__ out)
{
    extern __shared__ float sm[];
    float*  Qs  = sm + SM_Q;
    int*    cus = (int*)(sm + SM_CUS);
    __half* KHs = (__half*)((char*)sm + SM_KH_B);
    const uint32_t sb = smem_u32(sm);

    const int tid = threadIdx.x, wid = tid >> 5, lane = tid & 31;
    const int r = lane >> 2, c = lane & 3;
    const int qt = gridDim.x - 1 - blockIdx.x;    // heavy (late) q-tiles first
    const int q0 = qt * BQ;
    const int h = blockIdx.y, g = h >> 2;

    if (tid <= NSEQ) cus[tid] = cu[tid];

    const int ld_r = tid >> 5;        // 0..3; rows ld_r + 4j
    const int ld_d = tid & 31;

    int st = 0;
    #pragma unroll
    for (int j = 1; j < NSEQ; j++) st += (q0 >= cu[j]);
    const int first_kt = cu[st] >> 5;
    const int last_kt  = (q0 + BQ - 1) >> 5;

    // ---- prologue: cp.async V(first) into buf0; LDG K(first) into regs ----
    float4 kreg[8];
    {
        const float4* kg = (const float4*)(k + ((size_t)(first_kt * BK) * NGRP + g) * HDIM);
        const float4* vg = (const float4*)(v + ((size_t)(first_kt * BK) * NGRP + g) * HDIM);
        const uint32_t vb = sb + SM_V * 4;
        #pragma unroll
        for (int j = 0; j < 8; j++) {
            int rr = ld_r + j * 4;
            cpa16(vb + (rr * VSTRIDE + ld_d * 4) * 4, vg + (size_t)rr * (NGRP * HDIM / 4) + ld_d);
            kreg[j] = kg[(size_t)rr * (NGRP * HDIM / 4) + ld_d];
        }
        CP_COMMIT();
    }

    // ---- stage Q tile [64][128] fp32 ----
    {
        const float4* qg = (const float4*)(q + ((size_t)q0 * NHEAD + h) * HDIM);
        #pragma unroll
        for (int i = tid; i < BQ * 32; i += NTHR) {
            int rr = i >> 5, dd = i & 31;
            *(float4*)(Qs + rr * QSTRIDE + dd * 4) = qg[(size_t)rr * (NHEAD * HDIM / 4) + dd];
        }
    }
    __syncthreads();

    const int rb = wid * 16;

    // ---- cache Q fragments as packed fp16 (RN) for the whole KV loop ----
    uint32_t qa[8][4];
    #pragma unroll
    for (int kc = 0; kc < 8; kc++) {
        const float* b0 = Qs + (rb + r) * QSTRIDE + kc * 16;
        const float* b1 = b0 + 8 * QSTRIDE;
        qa[kc][0] = f2h2(b0[2 * c],     b0[2 * c + 1]);
        qa[kc][1] = f2h2(b1[2 * c],     b1[2 * c + 1]);
        qa[kc][2] = f2h2(b0[2 * c + 8], b0[2 * c + 9]);
        qa[kc][3] = f2h2(b1[2 * c + 8], b1[2 * c + 9]);
    }

    const int qp0 = q0 + rb + r;
    const int qp1 = qp0 + 8;
    int seg0 = 0, seg1 = 0;
    #pragma unroll
    for (int j = 1; j < NSEQ; j++) {
        seg0 += (qp0 >= cus[j]);
        seg1 += (qp1 >= cus[j]);
    }
    const int lo0g = cus[seg0], lo1g = cus[seg1];

    float o[16][4];
    #pragma unroll
    for (int nb = 0; nb < 16; nb++)
        o[nb][0] = o[nb][1] = o[nb][2] = o[nb][3] = 0.f;
    float lsum0 = 0.f, lsum1 = 0.f;

    int buf = 0;
    for (int kt = first_kt; kt <= last_kt; kt++, buf ^= 1) {
        const int kv0 = kt * BK;
        __half* KH = KHs + buf * (BK * KPADH);
        const float* VH = sm + SM_V + buf * (BK * VSTRIDE);

        // ---- STS K(kt): convert staged regs to fp16 (RN), write half[32][136] ----
        #pragma unroll
        for (int j = 0; j < 8; j++) {
            int rr = ld_r + j * 4;
            uint2 p;
            p.x = f2h2(kreg[j].x, kreg[j].y);
            p.y = f2h2(kreg[j].z, kreg[j].w);
            *(uint2*)(KH + rr * KPADH + ld_d * 4) = p;
        }
        CP_WAIT0();        // V(kt) complete
        __syncthreads();   // K/V visible; prior tile's readers done

        // ---- issue V(kt+1) cp.async; LDG K(kt+1) into regs (latency hidden) ----
        if (kt < last_kt) {
            const float4* kg = (const float4*)(k + ((size_t)(kv0 + BK) * NGRP + g) * HDIM);
            const float4* vg = (const float4*)(v + ((size_t)(kv0 + BK) * NGRP + g) * HDIM);
            const uint32_t vb = sb + (SM_V + (buf ^ 1) * BK * VSTRIDE) * 4;
            #pragma unroll
            for (int j = 0; j < 8; j++) {
                int rr = ld_r + j * 4;
                cpa16(vb + (rr * VSTRIDE + ld_d * 4) * 4, vg + (size_t)rr * (NGRP * HDIM / 4) + ld_d);
                kreg[j] = kg[(size_t)rr * (NGRP * HDIM / 4) + ld_d];
            }
            CP_COMMIT();
        }

        // ---- MMA1 (fp16 m16n8k16): S = Q * K^T ----
        float sacc[4][4];
        #pragma unroll
        for (int nb = 0; nb < 4; nb++)
            sacc[nb][0] = sacc[nb][1] = sacc[nb][2] = sacc[nb][3] = 0.f;

        #pragma unroll
        for (int kc = 0; kc < 8; kc++) {
            const __half* kb = KH + kc * 16 + 2 * c;
            #pragma unroll
            for (int nb = 0; nb < 4; nb++) {
                uint32_t b0 = *(const uint32_t*)(kb + (nb * 8 + r) * KPADH);
                uint32_t b1 = *(const uint32_t*)(kb + (nb * 8 + r) * KPADH + 8);
                mma16(sacc[nb], qa[kc], b0, b1);
            }
        }

        // ---- mask + exp; quantize P (tf32-RN) before summing -> consistent in MMA2 ----
        const int hi0 = qp0 - kv0, hi1 = qp1 - kv0;
        const int l0  = lo0g - kv0, l1 = lo1g - kv0;
        #pragma unroll
        for (int nb = 0; nb < 4; nb++) {
            const int j0 = nb * 8 + 2 * c, j1 = j0 + 1;
            float p0 = (j0 >= l0 && j0 <= hi0) ? tf32rn(ex2(sacc[nb][0] * COEF)) : 0.f;
            float p1 = (j1 >= l0 && j1 <= hi0) ? tf32rn(ex2(sacc[nb][1] * COEF)) : 0.f;
            float p2 = (j0 >= l1 && j0 <= hi1) ? tf32rn(ex2(sacc[nb][2] * COEF)) : 0.f;
            float p3 = (j1 >= l1 && j1 <= hi1) ? tf32rn(ex2(sacc[nb][3] * COEF)) : 0.f;
            lsum0 += p0 + p1;
            lsum1 += p2 + p3;
            sacc[nb][0] = p0; sacc[nb][1] = p1; sacc[nb][2] = p2; sacc[nb][3] = p3;
        }

        // ---- MMA2 (tf32): O += P * V  (P C-frag -> A-frag via shuffles; V raw fp32) ----
        const int s0 = (lane & ~3) | (c >> 1);
        const int s1 = s0 + 2;
        const bool odd = (c & 1);
        #pragma unroll
        for (int kc2 = 0; kc2 < 4; kc2++) {
            float t0 = __shfl_sync(0xffffffffu, sacc[kc2][0], s0);
            float t1 = __shfl_sync(0xffffffffu, sacc[kc2][1], s0);
            float t2 = __shfl_sync(0xffffffffu, sacc[kc2][2], s0);
            float t3 = __shfl_sync(0xffffffffu, sacc[kc2][3], s0);
            float u0 = __shfl_sync(0xffffffffu, sacc[kc2][0], s1);
            float u1 = __shfl_sync(0xffffffffu, sacc[kc2][1], s1);
            float u2 = __shfl_sync(0xffffffffu, sacc[kc2][2], s1);
            float u3 = __shfl_sync(0xffffffffu, sacc[kc2][3], s1);
            float pa[4];
            pa[0] = odd ? t1 : t0;
            pa[1] = odd ? t3 : t2;
            pa[2] = odd ? u1 : u0;
            pa[3] = odd ? u3 : u2;

            const float* vb = VH + (kc2 * 8 + c) * VSTRIDE + r;
            #pragma unroll
            for (int nb = 0; nb < 16; nb++) {
                float b0 = vb[nb * 8];
                float b1 = vb[nb * 8 + 4 * VSTRIDE];
                mma8(o[nb], pa, b0, b1);
            }
        }
    }

    // ---- epilogue ----
    lsum0 += __shfl_xor_sync(0xffffffffu, lsum0, 1);
    lsum0 += __shfl_xor_sync(0xffffffffu, lsum0, 2);
    lsum1 += __shfl_xor_sync(0xffffffffu, lsum1, 1);
    lsum1 += __shfl_xor_sync(0xffffffffu, lsum1, 2);
    const float inv0 = 1.0f / lsum0;
    const float inv1 = 1.0f / lsum1;

    float* o0 = out + ((size_t)qp0 * NHEAD + h) * HDIM;
    float* o1 = out + ((size_t)qp1 * NHEAD + h) * HDIM;
    #pragma unroll
    for (int nb = 0; nb < 16; nb++) {
        const int j0 = nb * 8 + 2 * c;
        *(float2*)(o0 + j0) = make_float2(o[nb][0] * inv0, o[nb][1] * inv0);
        *(float2*)(o1 + j0) = make_float2(o[nb][2] * inv1, o[nb][3] * inv1);
    }
}

extern "C" void kernel_launch(void* const* d_in, const int* in_sizes, int n_in,
                              void* d_out, int out_size)
{
    const float* q  = (const float*)d_in[0];
    const float* k  = (const float*)d_in[1];
    const float* v  = (const float*)d_in[2];
    const int*   cu = (const int*)d_in[3];
    float* out = (float*)d_out;

    static bool attr_set = false;
    if (!attr_set) {
        cudaFuncSetAttribute(fa_mma16_kernel,
                             cudaFuncAttributeMaxDynamicSharedMemorySize, SMEM_BYTES);
        attr_set = true;
    }

    dim3 grid(T_TOK / BQ, NHEAD);
    fa_mma16_kernel<<<grid, NTHR, SMEM_BYTES>>>(q, k, v, cu, out);
}

// round 17
// speedup vs baseline: 2.5583x; 1.2948x over previous
#include <cuda_runtime.h>
#include <cuda_fp16.h>
#include <cstdint>

#define T_TOK 4096
#define NHEAD 16
#define NGRP  4
#define HDIM  128
#define NSEQ  8
#define BQ    64
#define BK    32
#define NTHR  128

#define QSTRIDE 132
#define KPADH   136    // halfs per K row; word-stride 68 ≡ 4 (mod 32) -> frag banks 4r+c
#define VSH     136    // uint32 (half2) stride for VT; ≡ 8 (mod 32) -> frag banks 8c+r

static constexpr float COEF = 0.08838834764831845f * 1.4426950408889634f;

// smem bytes: Qs[64][132] fp32 | KH[2][32][136] half | VT[2][16][136] half2 | cus
#define SM_Q_B    0
#define SM_KH_B   (BQ * QSTRIDE * 4)                    // 33792
#define SM_VT_B   (SM_KH_B + 2 * BK * KPADH * 2)        // +17408 = 51200
#define SM_CUS_B  (SM_VT_B + 2 * (BK/2) * VSH * 4)      // +17408 = 68608
#define SMEM_BYTES (SM_CUS_B + 64)                      // 68672 -> 2 CTAs/SM

__device__ __forceinline__ float ex2(float x) {
    float y;
    asm("ex2.approx.ftz.f32 %0, %1;" : "=f"(y) : "f"(x));
    return y;
}
__device__ __forceinline__ uint32_t f2h2(float x, float y) {
    __half2 h = __floats2half2_rn(x, y);
    return *(uint32_t*)&h;
}

// fp16 m16n8k16: D(f32) += A(f16) * B(f16)
__device__ __forceinline__ void mma16(float d[4], const uint32_t a[4], uint32_t b0, uint32_t b1) {
    asm volatile(
        "mma.sync.aligned.m16n8k16.row.col.f32.f16.f16.f32 "
        "{%0,%1,%2,%3}, {%4,%5,%6,%7}, {%8,%9}, {%0,%1,%2,%3};"
        : "+f"(d[0]), "+f"(d[1]), "+f"(d[2]), "+f"(d[3])
        : "r"(a[0]), "r"(a[1]), "r"(a[2]), "r"(a[3]), "r"(b0), "r"(b1));
}

__global__ __launch_bounds__(NTHR, 2)
void fa_mma17_kernel(const float* __restrict__ q, const float* __restrict__ k,
                     const float* __restrict__ v, const int* __restrict__ cu,
                     float* __restrict__ out)
{
    extern __shared__ char smc[];
    float*    Qs  = (float*)(smc + SM_Q_B);
    __half*   KHs = (__half*)(smc + SM_KH_B);
    uint32_t* VTs = (uint32_t*)(smc + SM_VT_B);
    int*      cus = (int*)(smc + SM_CUS_B);

    const int tid = threadIdx.x, wid = tid >> 5, lane = tid & 31;
    const int r = lane >> 2, c = lane & 3;
    const int qt = gridDim.x - 1 - blockIdx.x;    // heavy (late) q-tiles first
    const int q0 = qt * BQ;
    const int h = blockIdx.y, g = h >> 2;

    if (tid <= NSEQ) cus[tid] = cu[tid];

    const int ld_r = tid >> 5;        // 0..3
    const int ld_d = tid & 31;

    int st = 0;
    #pragma unroll
    for (int j = 1; j < NSEQ; j++) st += (q0 >= cu[j]);
    const int first_kt = cu[st] >> 5;
    const int last_kt  = (q0 + BQ - 1) >> 5;

    // ---- prologue: LDG K(first) and V(first) into regs ----
    // K: thread covers rows ld_r+4j (j=0..7), float4 chunk ld_d.
    // V: thread covers token-pair k2 = ld_r+4j (j=0..3), rows 2k2/2k2+1, chunk ld_d.
    float4 kreg[8], vreg[8];
    {
        const float4* kg = (const float4*)(k + ((size_t)(first_kt * BK) * NGRP + g) * HDIM);
        const float4* vg = (const float4*)(v + ((size_t)(first_kt * BK) * NGRP + g) * HDIM);
        #pragma unroll
        for (int j = 0; j < 8; j++)
            kreg[j] = kg[(size_t)(ld_r + j * 4) * (NGRP * HDIM / 4) + ld_d];
        #pragma unroll
        for (int j = 0; j < 4; j++) {
            int k2 = ld_r + j * 4;
            vreg[2 * j]     = vg[(size_t)(2 * k2)     * (NGRP * HDIM / 4) + ld_d];
            vreg[2 * j + 1] = vg[(size_t)(2 * k2 + 1) * (NGRP * HDIM / 4) + ld_d];
        }
    }

    // ---- stage Q tile [64][128] fp32 ----
    {
        const float4* qg = (const float4*)(q + ((size_t)q0 * NHEAD + h) * HDIM);
        #pragma unroll
        for (int i = tid; i < BQ * 32; i += NTHR) {
            int rr = i >> 5, dd = i & 31;
            *(float4*)(Qs + rr * QSTRIDE + dd * 4) = qg[(size_t)rr * (NHEAD * HDIM / 4) + dd];
        }
    }
    __syncthreads();

    const int rb = wid * 16;

    // ---- cache Q fragments as packed fp16 (RN) for the whole KV loop ----
    uint32_t qa[8][4];
    #pragma unroll
    for (int kc = 0; kc < 8; kc++) {
        const float* b0 = Qs + (rb + r) * QSTRIDE + kc * 16;
        const float* b1 = b0 + 8 * QSTRIDE;
        qa[kc][0] = f2h2(b0[2 * c],     b0[2 * c + 1]);
        qa[kc][1] = f2h2(b1[2 * c],     b1[2 * c + 1]);
        qa[kc][2] = f2h2(b0[2 * c + 8], b0[2 * c + 9]);
        qa[kc][3] = f2h2(b1[2 * c + 8], b1[2 * c + 9]);
    }

    const int qp0 = q0 + rb + r;
    const int qp1 = qp0 + 8;
    int seg0 = 0, seg1 = 0;
    #pragma unroll
    for (int j = 1; j < NSEQ; j++) {
        seg0 += (qp0 >= cus[j]);
        seg1 += (qp1 >= cus[j]);
    }
    const int lo0g = cus[seg0], lo1g = cus[seg1];

    float o[16][4];
    #pragma unroll
    for (int nb = 0; nb < 16; nb++)
        o[nb][0] = o[nb][1] = o[nb][2] = o[nb][3] = 0.f;
    float lsum0 = 0.f, lsum1 = 0.f;

    int buf = 0;
    for (int kt = first_kt; kt <= last_kt; kt++, buf ^= 1) {
        const int kv0 = kt * BK;
        __half*   KH = KHs + buf * (BK * KPADH);
        uint32_t* VT = VTs + buf * ((BK / 2) * VSH);

        // ---- STS K (fp16, [32][136] half) and V (transposed half2 pairs) ----
        #pragma unroll
        for (int j = 0; j < 8; j++) {
            int rr = ld_r + j * 4;
            uint2 p;
            p.x = f2h2(kreg[j].x, kreg[j].y);
            p.y = f2h2(kreg[j].z, kreg[j].w);
            *(uint2*)(KH + rr * KPADH + ld_d * 4) = p;
        }
        #pragma unroll
        for (int j = 0; j < 4; j++) {
            int k2 = ld_r + j * 4;
            float4 v0 = vreg[2 * j], v1 = vreg[2 * j + 1];
            uint4 pk;
            pk.x = f2h2(v0.x, v1.x);   // VT[k2][n] = (V[2k2][n], V[2k2+1][n])
            pk.y = f2h2(v0.y, v1.y);
            pk.z = f2h2(v0.z, v1.z);
            pk.w = f2h2(v0.w, v1.w);
            *(uint4*)(VT + k2 * VSH + ld_d * 4) = pk;
        }
        __syncthreads();   // single barrier per tile (double buffer; hazard-safe)

        // ---- LDG next tile into regs (latency hidden behind compute) ----
        if (kt < last_kt) {
            const float4* kg = (const float4*)(k + ((size_t)(kv0 + BK) * NGRP + g) * HDIM);
            const float4* vg = (const float4*)(v + ((size_t)(kv0 + BK) * NGRP + g) * HDIM);
            #pragma unroll
            for (int j = 0; j < 8; j++)
                kreg[j] = kg[(size_t)(ld_r + j * 4) * (NGRP * HDIM / 4) + ld_d];
            #pragma unroll
            for (int j = 0; j < 4; j++) {
                int k2 = ld_r + j * 4;
                vreg[2 * j]     = vg[(size_t)(2 * k2)     * (NGRP * HDIM / 4) + ld_d];
                vreg[2 * j + 1] = vg[(size_t)(2 * k2 + 1) * (NGRP * HDIM / 4) + ld_d];
            }
        }

        // ---- MMA1 (fp16 k16): S = Q * K^T ----
        float sacc[4][4];
        #pragma unroll
        for (int nb = 0; nb < 4; nb++)
            sacc[nb][0] = sacc[nb][1] = sacc[nb][2] = sacc[nb][3] = 0.f;

        #pragma unroll
        for (int kc = 0; kc < 8; kc++) {
            const __half* kb = KH + kc * 16 + 2 * c;
            #pragma unroll
            for (int nb = 0; nb < 4; nb++) {
                uint32_t b0 = *(const uint32_t*)(kb + (nb * 8 + r) * KPADH);
                uint32_t b1 = *(const uint32_t*)(kb + (nb * 8 + r) * KPADH + 8);
                mma16(sacc[nb], qa[kc], b0, b1);
            }
        }

        // ---- mask + exp; pack P to fp16 A-fragments (C-frag layout == A-frag layout!) ----
        const int hi0 = qp0 - kv0, hi1 = qp1 - kv0;
        const int l0  = lo0g - kv0, l1 = lo1g - kv0;
        uint32_t pa[2][4];
        #pragma unroll
        for (int nb = 0; nb < 4; nb++) {
            const int j0 = nb * 8 + 2 * c, j1 = j0 + 1;
            float p0 = (j0 >= l0 && j0 <= hi0) ? ex2(sacc[nb][0] * COEF) : 0.f;
            float p1 = (j1 >= l0 && j1 <= hi0) ? ex2(sacc[nb][1] * COEF) : 0.f;
            float p2 = (j0 >= l1 && j0 <= hi1) ? ex2(sacc[nb][2] * COEF) : 0.f;
            float p3 = (j1 >= l1 && j1 <= hi1) ? ex2(sacc[nb][3] * COEF) : 0.f;
            lsum0 += p0 + p1;
            lsum1 += p2 + p3;
            pa[nb >> 1][(nb & 1) ? 2 : 0] = f2h2(p0, p1);
            pa[nb >> 1][(nb & 1) ? 3 : 1] = f2h2(p2, p3);
        }

        // ---- MMA2 (fp16 k16): O += P * V  (V from transposed half2 tile; no shuffles) ----
        #pragma unroll
        for (int kc2 = 0; kc2 < 2; kc2++) {
            const uint32_t* vb = VT + (kc2 * 8 + c) * VSH;
            #pragma unroll
            for (int nb = 0; nb < 16; nb++) {
                uint32_t b0 = vb[nb * 8 + r];
                uint32_t b1 = vb[4 * VSH + nb * 8 + r];
                mma16(o[nb], pa[kc2], b0, b1);
            }
        }
    }

    // ---- epilogue ----
    lsum0 += __shfl_xor_sync(0xffffffffu, lsum0, 1);
    lsum0 += __shfl_xor_sync(0xffffffffu, lsum0, 2);
    lsum1 += __shfl_xor_sync(0xffffffffu, lsum1, 1);
    lsum1 += __shfl_xor_sync(0xffffffffu, lsum1, 2);
    const float inv0 = 1.0f / lsum0;
    const float inv1 = 1.0f / lsum1;

    float* o0 = out + ((size_t)qp0 * NHEAD + h) * HDIM;
    float* o1 = out + ((size_t)qp1 * NHEAD + h) * HDIM;
    #pragma unroll
    for (int nb = 0; nb < 16; nb++) {
        const int j0 = nb * 8 + 2 * c;
        *(float2*)(o0 + j0) = make_float2(o[nb][0] * inv0, o[nb][1] * inv0);
        *(float2*)(o1 + j0) = make_float2(o[nb][2] * inv1, o[nb][3] * inv1);
    }
}

extern "C" void kernel_launch(void* const* d_in, const int* in_sizes, int n_in,
                              void* d_out, int out_size)
{
    const float* q  = (const float*)d_in[0];
    const float* k  = (const float*)d_in[1];
    const float* v  = (const float*)d_in[2];
    const int*   cu = (const int*)d_in[3];
    float* out = (float*)d_out;

    static bool attr_set = false;
    if (!attr_set) {
        cudaFuncSetAttribute(fa_mma17_kernel,
                             cudaFuncAttributeMaxDynamicSharedMemorySize, SMEM_BYTES);
        attr_set = true;
    }

    dim3 grid(T_TOK / BQ, NHEAD);
    fa_mma17_kernel<<<grid, NTHR, SMEM_BYTES>>>(q, k, v, cu, out);
}